// round 16
// baseline (speedup 1.0000x reference)
#include <cuda_runtime.h>
#include <cuda_bf16.h>
#include <cuda_fp8.h>
#include <math.h>

#define TT 256
#define BB 128
#define EE 256
#define HH 512
#define NK 7
#define NCTAS 64

#define SPB 528    // h / Whh smem row stride (bytes)
#define SPX 272    // x / Wih smem row stride (bytes)
#define XBUFB 34816
#define OFF_W 67584     // after h buffer 128*528
#define OFF_X 101376    // after Whh 64*528
#define OFF_WX 171008   // after X 2*34816
#define RC_SMEM 188416  // + Wih 64*272

__device__ __align__(256) unsigned char g_X8[8388608];   // [t][b][e] fp8 = x*16
__device__ __align__(256) unsigned char g_h8[33554432];  // [dir][t][b][k] fp8 = h*16
__device__ float g_em[229376];
__device__ float g_lossB[BB];
__device__ unsigned g_flag[8];                           // [dir*4+chunk], +8 per step

__device__ __forceinline__ float tanh_fast(float x) {
    float y;
    asm("tanh.approx.f32 %0, %1;" : "=f"(y) : "f"(x));
    return y;
}
__device__ __forceinline__ float sigmoid_fast(float x) {
    return 0.5f * tanh_fast(0.5f * x) + 0.5f;
}

__device__ __forceinline__ unsigned smem_u32(const void* p) {
    return (unsigned)__cvta_generic_to_shared(p);
}

__device__ __forceinline__ void ldsm4(unsigned addr, unsigned* r) {
    asm volatile("ldmatrix.sync.aligned.m8n8.x4.shared.b16 {%0,%1,%2,%3}, [%4];"
                 : "=r"(r[0]), "=r"(r[1]), "=r"(r[2]), "=r"(r[3]) : "r"(addr));
}

__device__ __forceinline__ void mma_fp8(float* c, const unsigned* a, unsigned b0, unsigned b1) {
    asm volatile(
        "mma.sync.aligned.m16n8k32.row.col.f32.e4m3.e4m3.f32 "
        "{%0,%1,%2,%3},{%4,%5,%6,%7},{%8,%9},{%0,%1,%2,%3};"
        : "+f"(c[0]), "+f"(c[1]), "+f"(c[2]), "+f"(c[3])
        : "r"(a[0]), "r"(a[1]), "r"(a[2]), "r"(a[3]), "r"(b0), "r"(b1));
}

__device__ __forceinline__ void cp_async16(unsigned saddr, const void* gaddr) {
    asm volatile("cp.async.cg.shared.global [%0], [%1], 16;" :: "r"(saddr), "l"(gaddr));
}
__device__ __forceinline__ void cp_commit() { asm volatile("cp.async.commit_group;"); }
__device__ __forceinline__ void cp_wait3() { asm volatile("cp.async.wait_group 3;"); }
__device__ __forceinline__ void cp_wait2() { asm volatile("cp.async.wait_group 2;"); }
__device__ __forceinline__ void cp_wait1() { asm volatile("cp.async.wait_group 1;"); }
__device__ __forceinline__ void cp_wait0() { asm volatile("cp.async.wait_group 0;"); }

__device__ __forceinline__ float2 fp8x2_to_float2(unsigned short v) {
    unsigned hp;
    asm("cvt.rn.f16x2.e4m3x2 %0, %1;" : "=r"(hp) : "h"(v));
    __half2 hh = *(__half2*)&hp;
    return __half22float2(hh);
}

// =============== kernel 0: reset publish flags ======================================
__global__ void reset_flags_k() {
    if (threadIdx.x < 8) g_flag[threadIdx.x] = 0u;
}

// =============== kernel 1: embed gather -> fp8 X (x16) ==============================
__global__ void __launch_bounds__(256) embed_gather(
    const int* __restrict__ inputData, const float* __restrict__ embed)
{
    const int eg_t = blockIdx.x;
    const int eg_b = blockIdx.y * 8 + (threadIdx.x >> 5);
    const int eg_lane = threadIdx.x & 31;
    const int eg_row = inputData[eg_t * BB + eg_b];
    const float4* eg_src = (const float4*)(embed + (size_t)eg_row * EE) + eg_lane * 2;
    float4 v0 = __ldg(eg_src);
    float4 v1 = __ldg(eg_src + 1);
    v0.x *= 16.f; v0.y *= 16.f; v0.z *= 16.f; v0.w *= 16.f;
    v1.x *= 16.f; v1.y *= 16.f; v1.z *= 16.f; v1.w *= 16.f;
    __nv_fp8x4_e4m3 p0(v0);
    __nv_fp8x4_e4m3 p1(v1);
    uint2 ov;
    ov.x = *(unsigned*)&p0;
    ov.y = *(unsigned*)&p1;
    *(uint2*)(g_X8 + ((size_t)eg_t * BB + eg_b) * EE + eg_lane * 8) = ov;
}

// =============== kernel 2: persistent fused BiLSTM, 64 CTAs, N=64 per CTA ===========
__global__ void __launch_bounds__(256, 1) recurrent(
    const float* __restrict__ WhhF, const float* __restrict__ WhhB,
    const float* __restrict__ WihF, const float* __restrict__ WihB,
    const float* __restrict__ bihF, const float* __restrict__ bhhF,
    const float* __restrict__ bihB, const float* __restrict__ bhhB)
{
    extern __shared__ __align__(16) unsigned char rc_smem[];

    const int rc_tid  = threadIdx.x;
    const int rc_warp = rc_tid >> 5;
    const int rc_lane = rc_tid & 31;
    const int rc_bid  = blockIdx.x;
    const int dir     = rc_bid >> 5;
    const int cidx    = rc_bid & 31;
    const int hc0     = cidx * 16;
    const int rc_myck = cidx >> 3;
    const float* __restrict__ Whh = dir ? WhhB : WhhF;
    const float* __restrict__ Wih = dir ? WihB : WihF;
    const float* __restrict__ bih = dir ? bihB : bihF;
    const float* __restrict__ bhh = dir ? bhhB : bhhF;

    // one-time weight loads (x64 into fp8 sweet spot); W-row r: gate=r>>4, hcl=r&15
    for (int wi = rc_tid; wi < 64 * 512; wi += 256) {
        int wrow = wi >> 9;
        int wk = wi & 511;
        int wj = (wrow >> 4) * HH + hc0 + (wrow & 15);
        __nv_fp8_e4m3 wv(Whh[(size_t)wj * HH + wk] * 64.0f);
        rc_smem[OFF_W + wrow * SPB + wk] = *(unsigned char*)&wv;
    }
    for (int wi = rc_tid; wi < 64 * 256; wi += 256) {
        int wrow = wi >> 8;
        int wk = wi & 255;
        int wj = (wrow >> 4) * HH + hc0 + (wrow & 15);
        __nv_fp8_e4m3 wv(Wih[(size_t)wj * EE + wk] * 64.0f);
        rc_smem[OFF_WX + wrow * SPX + wk] = *(unsigned char*)&wv;
    }

    const int rc_q  = rc_lane & 3;
    const int rc_rq = rc_lane >> 2;
    const int rc_bl = rc_warp * 16 + rc_rq;

    // bias[gate][half][colparity]; j = g*HH + hc0 + half*8 + 2q + cp
    float bias_r[4][2][2];
#pragma unroll
    for (int gi = 0; gi < 4; gi++) {
#pragma unroll
        for (int hf = 0; hf < 2; hf++) {
#pragma unroll
            for (int cp = 0; cp < 2; cp++) {
                int bj = gi * HH + hc0 + hf * 8 + 2 * rc_q + cp;
                bias_r[gi][hf][cp] = bih[bj] + bhh[bj];
            }
        }
    }

    const unsigned rc_base = smem_u32(rc_smem);
    const unsigned rc_ha = rc_base +
        (unsigned)((rc_warp * 16 + (rc_lane & 15)) * SPB + (rc_lane >> 4) * 16);
    const int rc_brow = ((rc_lane >> 4) << 3) + (rc_lane & 7);
    const int rc_bk = ((rc_lane >> 3) & 1) * 16;
    unsigned rc_wh[4];
    unsigned rc_wx[4];
#pragma unroll
    for (int pt = 0; pt < 4; pt++) {
        rc_wh[pt] = rc_base + OFF_W + (unsigned)((pt * 16 + rc_brow) * SPB + rc_bk);
        rc_wx[pt] = rc_base + OFF_WX + (unsigned)((pt * 16 + rc_brow) * SPX + rc_bk);
    }
    const unsigned rc_xa0 = rc_base + OFF_X +
        (unsigned)((rc_warp * 16 + (rc_lane & 15)) * SPX + (rc_lane >> 4) * 16);

    // preload X[t0] into buffer 0
    {
        const int t0 = dir ? (TT - 1) : 0;
        const unsigned char* xsrc = g_X8 + (size_t)t0 * BB * EE;
#pragma unroll
        for (int li = 0; li < 8; li++) {
            int lv = li * 256 + rc_tid;
            int lrow = lv >> 4;
            int lu = lv & 15;
            cp_async16(rc_base + OFF_X + (unsigned)(lrow * SPX + lu * 16),
                       (const void*)(xsrc + lrow * EE + lu * 16));
        }
        cp_commit();
        cp_wait0();
    }
    __syncthreads();

    float rc_c[4][2];
#pragma unroll
    for (int pp = 0; pp < 4; pp++) {
        rc_c[pp][0] = 0.f;
        rc_c[pp][1] = 0.f;
    }

    for (int s = 0; s < TT; s++) {
        const int t = dir ? (TT - 1 - s) : s;
        const int cur = s & 1;
        const unsigned xcur = rc_xa0 + (unsigned)(cur * XBUFB);

        // prefetch next step's X
        if (s + 1 < TT) {
            const int tn = dir ? (t - 1) : (t + 1);
            const unsigned char* xsrc = g_X8 + (size_t)tn * BB * EE;
            const unsigned xdst = rc_base + OFF_X + (unsigned)((cur ^ 1) * XBUFB);
#pragma unroll
            for (int li = 0; li < 8; li++) {
                int lv = li * 256 + rc_tid;
                int lrow = lv >> 4;
                int lu = lv & 15;
                cp_async16(xdst + (unsigned)(lrow * SPX + lu * 16),
                           (const void*)(xsrc + lrow * EE + lu * 16));
            }
            cp_commit();
        }

        float rc_acc[8][4];
#pragma unroll
        for (int ti = 0; ti < 8; ti++) {
#pragma unroll
            for (int pi = 0; pi < 4; pi++) rc_acc[ti][pi] = 0.0f;
        }

        if (s > 0) {
            const int tp = dir ? (t + 1) : (t - 1);
            const unsigned char* rc_src = g_h8 + (size_t)(dir * TT + tp) * BB * HH;
            const unsigned rc_need = (unsigned)(8 * s);

            // warps 4-7 overlap X-mma with the polls of warps 0-3
            if (rc_warp >= 4) {
#pragma unroll
                for (int ks = 0; ks < 8; ks++) {
                    unsigned xaf[4];
                    ldsm4(xcur + ks * 32, xaf);
#pragma unroll
                    for (int pt = 0; pt < 4; pt++) {
                        unsigned xbf[4];
                        ldsm4(rc_wx[pt] + ks * 32, xbf);
                        mma_fp8(rc_acc[2 * pt], xaf, xbf[0], xbf[1]);
                        mma_fp8(rc_acc[2 * pt + 1], xaf, xbf[2], xbf[3]);
                    }
                }
            } else if (rc_lane == 0) {
                const unsigned* fp = &g_flag[dir * 4 + rc_warp];
                unsigned fv = 0;
                do {
                    asm volatile("ld.acquire.gpu.u32 %0, [%1];" : "=r"(fv) : "l"(fp) : "memory");
                } while (fv < rc_need);
            }
            __syncthreads();

            // issue 4 h-chunk groups
#pragma unroll
            for (int ck = 0; ck < 4; ck++) {
#pragma unroll
                for (int li = 0; li < 4; li++) {
                    int lv = li * 256 + rc_tid;
                    int lrow = lv >> 3;
                    int lu = lv & 7;
                    cp_async16(rc_base + (unsigned)(lrow * SPB + ck * 128 + lu * 16),
                               (const void*)(rc_src + lrow * 512 + ck * 128 + lu * 16));
                }
                cp_commit();
            }

            // warps 0-3 do their X-mma while h chunks are in flight
            if (rc_warp < 4) {
#pragma unroll
                for (int ks = 0; ks < 8; ks++) {
                    unsigned xaf[4];
                    ldsm4(xcur + ks * 32, xaf);
#pragma unroll
                    for (int pt = 0; pt < 4; pt++) {
                        unsigned xbf[4];
                        ldsm4(rc_wx[pt] + ks * 32, xbf);
                        mma_fp8(rc_acc[2 * pt], xaf, xbf[0], xbf[1]);
                        mma_fp8(rc_acc[2 * pt + 1], xaf, xbf[2], xbf[3]);
                    }
                }
            }

            cp_wait3();
            __syncthreads();
#pragma unroll
            for (int kk = 0; kk < 4; kk++) {
                unsigned haf[4];
                ldsm4(rc_ha + kk * 32, haf);
#pragma unroll
                for (int pt = 0; pt < 4; pt++) {
                    unsigned hbf[4];
                    ldsm4(rc_wh[pt] + kk * 32, hbf);
                    mma_fp8(rc_acc[2 * pt], haf, hbf[0], hbf[1]);
                    mma_fp8(rc_acc[2 * pt + 1], haf, hbf[2], hbf[3]);
                }
            }
            cp_wait2();
            __syncthreads();
#pragma unroll
            for (int kk = 4; kk < 8; kk++) {
                unsigned haf[4];
                ldsm4(rc_ha + kk * 32, haf);
#pragma unroll
                for (int pt = 0; pt < 4; pt++) {
                    unsigned hbf[4];
                    ldsm4(rc_wh[pt] + kk * 32, hbf);
                    mma_fp8(rc_acc[2 * pt], haf, hbf[0], hbf[1]);
                    mma_fp8(rc_acc[2 * pt + 1], haf, hbf[2], hbf[3]);
                }
            }
            cp_wait1();
            __syncthreads();
#pragma unroll
            for (int kk = 8; kk < 12; kk++) {
                unsigned haf[4];
                ldsm4(rc_ha + kk * 32, haf);
#pragma unroll
                for (int pt = 0; pt < 4; pt++) {
                    unsigned hbf[4];
                    ldsm4(rc_wh[pt] + kk * 32, hbf);
                    mma_fp8(rc_acc[2 * pt], haf, hbf[0], hbf[1]);
                    mma_fp8(rc_acc[2 * pt + 1], haf, hbf[2], hbf[3]);
                }
            }
            cp_wait0();
            __syncthreads();
#pragma unroll
            for (int kk = 12; kk < 16; kk++) {
                unsigned haf[4];
                ldsm4(rc_ha + kk * 32, haf);
#pragma unroll
                for (int pt = 0; pt < 4; pt++) {
                    unsigned hbf[4];
                    ldsm4(rc_wh[pt] + kk * 32, hbf);
                    mma_fp8(rc_acc[2 * pt], haf, hbf[0], hbf[1]);
                    mma_fp8(rc_acc[2 * pt + 1], haf, hbf[2], hbf[3]);
                }
            }
        } else {
#pragma unroll
            for (int ks = 0; ks < 8; ks++) {
                unsigned xaf[4];
                ldsm4(xcur + ks * 32, xaf);
#pragma unroll
                for (int pt = 0; pt < 4; pt++) {
                    unsigned xbf[4];
                    ldsm4(rc_wx[pt] + ks * 32, xbf);
                    mma_fp8(rc_acc[2 * pt], xaf, xbf[0], xbf[1]);
                    mma_fp8(rc_acc[2 * pt + 1], xaf, xbf[2], xbf[3]);
                }
            }
            cp_wait0();
            __syncthreads();
        }

        // epilogue: tile ti = 2*gate + half; gates = acc/1024 + bias
        float rc_h[4][2];
#pragma unroll
        for (int pp = 0; pp < 4; pp++) {
#pragma unroll
            for (int hf = 0; hf < 2; hf++) {
                const float ksc = 0.0009765625f;
                float pgi = rc_acc[0 + hf][pp] * ksc + bias_r[0][hf][pp & 1];
                float pgf = rc_acc[2 + hf][pp] * ksc + bias_r[1][hf][pp & 1];
                float pgg = rc_acc[4 + hf][pp] * ksc + bias_r[2][hf][pp & 1];
                float pgo = rc_acc[6 + hf][pp] * ksc + bias_r[3][hf][pp & 1];
                float piv = sigmoid_fast(pgi);
                float pfv = sigmoid_fast(pgf);
                float pgv = tanh_fast(pgg);
                float pov = sigmoid_fast(pgo);
                rc_c[pp][hf] = pfv * rc_c[pp][hf] + piv * pgv;
                rc_h[pp][hf] = pov * tanh_fast(rc_c[pp][hf]);
            }
        }

#pragma unroll
        for (int pb = 0; pb < 2; pb++) {
            const size_t ho = ((size_t)(dir * TT + t) * BB + rc_bl + pb * 8) * HH + hc0 + 2 * rc_q;
#pragma unroll
            for (int hf = 0; hf < 2; hf++) {
                __nv_fp8x2_e4m3 pr(make_float2(rc_h[2 * pb][hf] * 16.0f,
                                               rc_h[2 * pb + 1][hf] * 16.0f));
                *(unsigned short*)(g_h8 + ho + hf * 8) = *(unsigned short*)&pr;
            }
        }

        __syncthreads();
        if (rc_tid == 0) {
            asm volatile("red.release.gpu.global.add.u32 [%0], %1;"
                         :: "l"(&g_flag[dir * 4 + rc_myck]), "r"(1u) : "memory");
        }
    }
}

// =============== kernel 3: emissions, warp per (t, 4 b's) ===========================
__global__ void __launch_bounds__(128) emissions_k(
    const float* __restrict__ linW, const float* __restrict__ linb)
{
    const int em_t = blockIdx.y;
    const int em_b0 = (blockIdx.x * 4 + (threadIdx.x >> 5)) * 4;
    const int em_lane = threadIdx.x & 31;

    float em_acc[4][NK];
#pragma unroll
    for (int bb = 0; bb < 4; bb++) {
#pragma unroll
        for (int kc = 0; kc < NK; kc++) em_acc[bb][kc] = 0.0f;
    }

#pragma unroll
    for (int dd = 0; dd < 2; dd++) {
        unsigned hw[4][4];
#pragma unroll
        for (int bb = 0; bb < 4; bb++) {
            uint4 hv = *(const uint4*)(g_h8 +
                ((size_t)(dd * TT + em_t) * BB + em_b0 + bb) * HH + em_lane * 16);
            hw[bb][0] = hv.x;
            hw[bb][1] = hv.y;
            hw[bb][2] = hv.z;
            hw[bb][3] = hv.w;
        }
        const float* wb = linW + dd * HH + em_lane * 16;
#pragma unroll
        for (int sub = 0; sub < 4; sub++) {
            float hfb[4][4];
#pragma unroll
            for (int bb = 0; bb < 4; bb++) {
                unsigned wd = hw[bb][sub];
                float2 f01 = fp8x2_to_float2((unsigned short)(wd & 0xffffu));
                float2 f23 = fp8x2_to_float2((unsigned short)(wd >> 16));
                hfb[bb][0] = f01.x;
                hfb[bb][1] = f01.y;
                hfb[bb][2] = f23.x;
                hfb[bb][3] = f23.y;
            }
#pragma unroll
            for (int kc = 0; kc < NK; kc++) {
                float4 w = __ldg((const float4*)(wb + kc * (2 * HH) + sub * 4));
#pragma unroll
                for (int bb = 0; bb < 4; bb++) {
                    em_acc[bb][kc] += hfb[bb][0] * w.x + hfb[bb][1] * w.y
                                    + hfb[bb][2] * w.z + hfb[bb][3] * w.w;
                }
            }
        }
    }
#pragma unroll
    for (int bb = 0; bb < 4; bb++) {
#pragma unroll
        for (int kc = 0; kc < NK; kc++) {
#pragma unroll
            for (int o = 16; o; o >>= 1)
                em_acc[bb][kc] += __shfl_xor_sync(0xffffffffu, em_acc[bb][kc], o);
        }
    }
    if (em_lane == 0) {
#pragma unroll
        for (int bb = 0; bb < 4; bb++) {
#pragma unroll
            for (int kc = 0; kc < NK; kc++) {
                g_em[((size_t)em_t * BB + em_b0 + bb) * NK + kc] =
                    em_acc[bb][kc] * 0.0625f + linb[kc];
            }
        }
    }
}

// =============== kernel 4: CRF score + forward algorithm =============================
__global__ void __launch_bounds__(32) crf_k(
    const int* __restrict__ labels, const float* __restrict__ trans,
    const float* __restrict__ startT, const float* __restrict__ endT)
{
    const int cb = blockIdx.x;
    const int cl = threadIdx.x;

    float csc = 0.0f;
    for (int ct = cl; ct < TT; ct += 32) {
        int clt = labels[cb * TT + ct];
        csc += g_em[((size_t)ct * BB + cb) * NK + clt];
        if (ct < TT - 1) csc += trans[clt * NK + labels[cb * TT + ct + 1]];
    }
#pragma unroll
    for (int o = 16; o; o >>= 1) csc += __shfl_down_sync(0xffffffffu, csc, o);

    const int ck = (cl < NK) ? cl : 0;
    float ctr[NK];
#pragma unroll
    for (int cj = 0; cj < NK; cj++) ctr[cj] = trans[cj * NK + ck];

    float calpha = startT[ck] + g_em[(size_t)cb * NK + ck];
    for (int ct = 1; ct < TT; ct++) {
        float cv[NK];
        float cm = -3.0e38f;
#pragma unroll
        for (int cj = 0; cj < NK; cj++) {
            cv[cj] = __shfl_sync(0xffffffffu, calpha, cj) + ctr[cj];
            cm = fmaxf(cm, cv[cj]);
        }
        float cs = 0.0f;
#pragma unroll
        for (int cj = 0; cj < NK; cj++) cs += __expf(cv[cj] - cm);
        calpha = cm + __logf(cs) + g_em[((size_t)ct * BB + cb) * NK + ck];
    }
    float cav = calpha + endT[ck];
    float cmm = cav;
#pragma unroll
    for (int cj = 0; cj < NK; cj++) cmm = fmaxf(cmm, __shfl_sync(0xffffffffu, cav, cj));
    float ce = (cl < NK) ? __expf(cav - cmm) : 0.0f;
#pragma unroll
    for (int o = 16; o; o >>= 1) ce += __shfl_down_sync(0xffffffffu, ce, o);

    if (cl == 0) {
        float clogZ = cmm + __logf(ce);
        float cscore = csc + startT[labels[cb * TT]] + endT[labels[cb * TT + TT - 1]];
        g_lossB[cb] = cscore - clogZ;
    }
}

// =============== kernel 5: deterministic final reduce ================================
__global__ void __launch_bounds__(128) final_reduce(float* out)
{
    __shared__ float fr_s[128];
    fr_s[threadIdx.x] = g_lossB[threadIdx.x];
    __syncthreads();
    for (int o = 64; o; o >>= 1) {
        if (threadIdx.x < o) fr_s[threadIdx.x] += fr_s[threadIdx.x + o];
        __syncthreads();
    }
    if (threadIdx.x == 0) out[0] = -fr_s[0];
}

// =============== launch ==============================================================
extern "C" void kernel_launch(void* const* d_in, const int* in_sizes, int n_in,
                              void* d_out, int out_size)
{
    const int*   inputData = (const int*)d_in[0];
    const int*   labels    = (const int*)d_in[1];
    const float* embed     = (const float*)d_in[2];
    const float* WihF = (const float*)d_in[3];
    const float* WhhF = (const float*)d_in[4];
    const float* bihF = (const float*)d_in[5];
    const float* bhhF = (const float*)d_in[6];
    const float* WihB = (const float*)d_in[7];
    const float* WhhB = (const float*)d_in[8];
    const float* bihB = (const float*)d_in[9];
    const float* bhhB = (const float*)d_in[10];
    const float* linW = (const float*)d_in[11];
    const float* linb = (const float*)d_in[12];
    const float* trans = (const float*)d_in[13];
    const float* startT = (const float*)d_in[14];
    const float* endT   = (const float*)d_in[15];

    cudaFuncSetAttribute(recurrent, cudaFuncAttributeMaxDynamicSharedMemorySize, RC_SMEM);

    reset_flags_k<<<1, 32>>>();
    embed_gather<<<dim3(TT, 16), 256>>>(inputData, embed);

    recurrent<<<NCTAS, 256, RC_SMEM>>>(WhhF, WhhB, WihF, WihB, bihF, bhhF, bihB, bhhB);

    emissions_k<<<dim3(8, TT), 128>>>(linW, linb);
    crf_k<<<BB, 32>>>(labels, trans, startT, endT);
    final_reduce<<<1, 128>>>((float*)d_out);
}

// round 17
// speedup vs baseline: 1.4199x; 1.4199x over previous
#include <cuda_runtime.h>
#include <cuda_bf16.h>
#include <cuda_fp8.h>
#include <math.h>

#define TT 256
#define BB 128
#define EE 256
#define HH 512
#define NK 7
#define NCTAS 128

#define SPB 528    // h smem row stride (bytes)
#define SPX 272    // x / Wih smem row stride (bytes)
#define XBUFB 34816
#define OFF_W 67584
#define OFF_X 84480
#define OFF_WX 154112
#define RC_SMEM 162816

__device__ __align__(256) unsigned char g_X8[8388608];   // [t][b][e] fp8 = x*16
__device__ __align__(256) unsigned char g_h8[33554432];  // [dir][t][b][k] fp8 = h*16
__device__ float g_em[229376];
__device__ float g_lossB[BB];
__device__ unsigned g_flag[8];                           // [dir*4+chunk], +16 per step

__device__ __forceinline__ float tanh_fast(float x) {
    float y;
    asm("tanh.approx.f32 %0, %1;" : "=f"(y) : "f"(x));
    return y;
}
__device__ __forceinline__ float sigmoid_fast(float x) {
    return 0.5f * tanh_fast(0.5f * x) + 0.5f;
}

__device__ __forceinline__ unsigned smem_u32(const void* p) {
    return (unsigned)__cvta_generic_to_shared(p);
}

__device__ __forceinline__ void ldsm4(unsigned addr, unsigned* r) {
    asm volatile("ldmatrix.sync.aligned.m8n8.x4.shared.b16 {%0,%1,%2,%3}, [%4];"
                 : "=r"(r[0]), "=r"(r[1]), "=r"(r[2]), "=r"(r[3]) : "r"(addr));
}

__device__ __forceinline__ void mma_fp8(float* c, const unsigned* a, unsigned b0, unsigned b1) {
    asm volatile(
        "mma.sync.aligned.m16n8k32.row.col.f32.e4m3.e4m3.f32 "
        "{%0,%1,%2,%3},{%4,%5,%6,%7},{%8,%9},{%0,%1,%2,%3};"
        : "+f"(c[0]), "+f"(c[1]), "+f"(c[2]), "+f"(c[3])
        : "r"(a[0]), "r"(a[1]), "r"(a[2]), "r"(a[3]), "r"(b0), "r"(b1));
}

__device__ __forceinline__ void cp_async16(unsigned saddr, const void* gaddr) {
    asm volatile("cp.async.cg.shared.global [%0], [%1], 16;" :: "r"(saddr), "l"(gaddr));
}
__device__ __forceinline__ void cp_commit() { asm volatile("cp.async.commit_group;"); }
__device__ __forceinline__ void cp_wait3() { asm volatile("cp.async.wait_group 3;"); }
__device__ __forceinline__ void cp_wait2() { asm volatile("cp.async.wait_group 2;"); }
__device__ __forceinline__ void cp_wait1() { asm volatile("cp.async.wait_group 1;"); }
__device__ __forceinline__ void cp_wait0() { asm volatile("cp.async.wait_group 0;"); }

__device__ __forceinline__ float2 fp8x2_to_float2(unsigned short v) {
    unsigned hp;
    asm("cvt.rn.f16x2.e4m3x2 %0, %1;" : "=r"(hp) : "h"(v));
    __half2 hh = *(__half2*)&hp;
    return __half22float2(hh);
}

// =============== kernel 0: reset publish flags ======================================
__global__ void reset_flags_k() {
    if (threadIdx.x < 8) g_flag[threadIdx.x] = 0u;
}

// =============== kernel 1: embed gather -> fp8 X (x16) ==============================
__global__ void __launch_bounds__(256) embed_gather(
    const int* __restrict__ inputData, const float* __restrict__ embed)
{
    const int eg_t = blockIdx.x;
    const int eg_b = blockIdx.y * 8 + (threadIdx.x >> 5);
    const int eg_lane = threadIdx.x & 31;
    const int eg_row = inputData[eg_t * BB + eg_b];
    const float4* eg_src = (const float4*)(embed + (size_t)eg_row * EE) + eg_lane * 2;
    float4 v0 = __ldg(eg_src);
    float4 v1 = __ldg(eg_src + 1);
    v0.x *= 16.f; v0.y *= 16.f; v0.z *= 16.f; v0.w *= 16.f;
    v1.x *= 16.f; v1.y *= 16.f; v1.z *= 16.f; v1.w *= 16.f;
    __nv_fp8x4_e4m3 p0(v0);
    __nv_fp8x4_e4m3 p1(v1);
    uint2 ov;
    ov.x = *(unsigned*)&p0;
    ov.y = *(unsigned*)&p1;
    *(uint2*)(g_X8 + ((size_t)eg_t * BB + eg_b) * EE + eg_lane * 8) = ov;
}

// =============== kernel 2: persistent fused BiLSTM (fp8 mma, dataflow) ==============
__global__ void __launch_bounds__(256, 1) recurrent(
    const float* __restrict__ WhhF, const float* __restrict__ WhhB,
    const float* __restrict__ WihF, const float* __restrict__ WihB,
    const float* __restrict__ bihF, const float* __restrict__ bhhF,
    const float* __restrict__ bihB, const float* __restrict__ bhhB)
{
    extern __shared__ __align__(16) unsigned char rc_smem[];

    const int rc_tid  = threadIdx.x;
    const int rc_warp = rc_tid >> 5;
    const int rc_lane = rc_tid & 31;
    const int rc_bid  = blockIdx.x;
    const int dir     = rc_bid >> 6;
    const int hc0     = (rc_bid & 63) * 8;
    const int rc_myck = (rc_bid & 63) >> 4;
    const float* __restrict__ Whh = dir ? WhhB : WhhF;
    const float* __restrict__ Wih = dir ? WihB : WihF;
    const float* __restrict__ bih = dir ? bihB : bihF;
    const float* __restrict__ bhh = dir ? bhhB : bhhF;

    // one-time weight loads (x64 into fp8 sweet spot)
    for (int wi = rc_tid; wi < 32 * 512; wi += 256) {
        int wrow = wi >> 9;
        int wk = wi & 511;
        int wj = (wrow >> 3) * HH + hc0 + (wrow & 7);
        __nv_fp8_e4m3 wv(Whh[(size_t)wj * HH + wk] * 64.0f);
        rc_smem[OFF_W + wrow * SPB + wk] = *(unsigned char*)&wv;
    }
    for (int wi = rc_tid; wi < 32 * 256; wi += 256) {
        int wrow = wi >> 8;
        int wk = wi & 255;
        int wj = (wrow >> 3) * HH + hc0 + (wrow & 7);
        __nv_fp8_e4m3 wv(Wih[(size_t)wj * EE + wk] * 64.0f);
        rc_smem[OFF_WX + wrow * SPX + wk] = *(unsigned char*)&wv;
    }

    const int rc_q  = rc_lane & 3;
    const int rc_rq = rc_lane >> 2;
    const int rc_bl = rc_warp * 16 + rc_rq;

    // bias registers: bias_r[gate][hcl&1] with hcl = 2q + (p&1)
    float bias_r[4][2];
#pragma unroll
    for (int gi = 0; gi < 4; gi++) {
#pragma unroll
        for (int hb = 0; hb < 2; hb++) {
            int bj = gi * HH + hc0 + 2 * rc_q + hb;
            bias_r[gi][hb] = bih[bj] + bhh[bj];
        }
    }

    const unsigned rc_base = smem_u32(rc_smem);
    const unsigned rc_ha = rc_base + (unsigned)((rc_warp * 16 + (rc_lane & 15)) * SPB + (rc_lane >> 4) * 16);
    const unsigned rc_wh0 = rc_base + OFF_W +
        (unsigned)(((((rc_lane >> 4) << 3) + (rc_lane & 7)) * SPB) + ((rc_lane >> 3) & 1) * 16);
    const unsigned rc_wh1 = rc_wh0 + 16 * SPB;
    const unsigned rc_xa0 = rc_base + OFF_X +
        (unsigned)((rc_warp * 16 + (rc_lane & 15)) * SPX + (rc_lane >> 4) * 16);
    const unsigned rc_wx0 = rc_base + OFF_WX +
        (unsigned)(((((rc_lane >> 4) << 3) + (rc_lane & 7)) * SPX) + ((rc_lane >> 3) & 1) * 16);
    const unsigned rc_wx1 = rc_wx0 + 16 * SPX;

    // preload X[t0] into buffer 0
    {
        const int t0 = dir ? (TT - 1) : 0;
        const unsigned char* xsrc = g_X8 + (size_t)t0 * BB * EE;
#pragma unroll
        for (int li = 0; li < 8; li++) {
            int lv = li * 256 + rc_tid;
            int lrow = lv >> 4;
            int lu = lv & 15;
            cp_async16(rc_base + OFF_X + (unsigned)(lrow * SPX + lu * 16),
                       (const void*)(xsrc + lrow * EE + lu * 16));
        }
        cp_commit();
        cp_wait0();
    }
    __syncthreads();

    float rc_c[4] = {0.f, 0.f, 0.f, 0.f};

    for (int s = 0; s < TT; s++) {
        const int t = dir ? (TT - 1 - s) : s;
        const int cur = s & 1;
        const unsigned xcur = rc_xa0 + (unsigned)(cur * XBUFB);

        // prefetch next step's X (independent of everything)
        if (s + 1 < TT) {
            const int tn = dir ? (t - 1) : (t + 1);
            const unsigned char* xsrc = g_X8 + (size_t)tn * BB * EE;
            const unsigned xdst = rc_base + OFF_X + (unsigned)((cur ^ 1) * XBUFB);
#pragma unroll
            for (int li = 0; li < 8; li++) {
                int lv = li * 256 + rc_tid;
                int lrow = lv >> 4;
                int lu = lv & 15;
                cp_async16(xdst + (unsigned)(lrow * SPX + lu * 16),
                           (const void*)(xsrc + lrow * EE + lu * 16));
            }
            cp_commit();
        }

        float rc_acc[4][4];
#pragma unroll
        for (int gi = 0; gi < 4; gi++) {
#pragma unroll
            for (int pi = 0; pi < 4; pi++) rc_acc[gi][pi] = 0.0f;
        }

        if (s > 0) {
            const int tp = dir ? (t + 1) : (t - 1);
            const unsigned char* rc_src = g_h8 + (size_t)(dir * TT + tp) * BB * HH;
            const unsigned rc_need = (unsigned)(16 * s);

            // warps 4-7 overlap X-mma with the polls of warps 0-3
            if (rc_warp >= 4) {
#pragma unroll
                for (int ks = 0; ks < 8; ks++) {
                    unsigned xaf[4];
                    unsigned xbf[4];
                    unsigned xcf[4];
                    ldsm4(xcur + ks * 32, xaf);
                    ldsm4(rc_wx0 + ks * 32, xbf);
                    ldsm4(rc_wx1 + ks * 32, xcf);
                    mma_fp8(rc_acc[0], xaf, xbf[0], xbf[1]);
                    mma_fp8(rc_acc[1], xaf, xbf[2], xbf[3]);
                    mma_fp8(rc_acc[2], xaf, xcf[0], xcf[1]);
                    mma_fp8(rc_acc[3], xaf, xcf[2], xcf[3]);
                }
            } else if (rc_lane == 0) {
                const unsigned* fp = &g_flag[dir * 4 + rc_warp];
                unsigned fv = 0;
                do {
                    asm volatile("ld.acquire.gpu.u32 %0, [%1];" : "=r"(fv) : "l"(fp) : "memory");
                } while (fv < rc_need);
            }
            __syncthreads();

            // issue 4 h-chunk groups
#pragma unroll
            for (int ck = 0; ck < 4; ck++) {
#pragma unroll
                for (int li = 0; li < 4; li++) {
                    int lv = li * 256 + rc_tid;
                    int lrow = lv >> 3;
                    int lu = lv & 7;
                    cp_async16(rc_base + (unsigned)(lrow * SPB + ck * 128 + lu * 16),
                               (const void*)(rc_src + lrow * 512 + ck * 128 + lu * 16));
                }
                cp_commit();
            }

            // warps 0-3 do their X-mma while h chunks are in flight
            if (rc_warp < 4) {
#pragma unroll
                for (int ks = 0; ks < 8; ks++) {
                    unsigned xaf[4];
                    unsigned xbf[4];
                    unsigned xcf[4];
                    ldsm4(xcur + ks * 32, xaf);
                    ldsm4(rc_wx0 + ks * 32, xbf);
                    ldsm4(rc_wx1 + ks * 32, xcf);
                    mma_fp8(rc_acc[0], xaf, xbf[0], xbf[1]);
                    mma_fp8(rc_acc[1], xaf, xbf[2], xbf[3]);
                    mma_fp8(rc_acc[2], xaf, xcf[0], xcf[1]);
                    mma_fp8(rc_acc[3], xaf, xcf[2], xcf[3]);
                }
            }

            cp_wait3();
            __syncthreads();
#pragma unroll
            for (int kk = 0; kk < 4; kk++) {
                unsigned haf[4];
                unsigned hbf[4];
                unsigned hcf[4];
                ldsm4(rc_ha + kk * 32, haf);
                ldsm4(rc_wh0 + kk * 32, hbf);
                ldsm4(rc_wh1 + kk * 32, hcf);
                mma_fp8(rc_acc[0], haf, hbf[0], hbf[1]);
                mma_fp8(rc_acc[1], haf, hbf[2], hbf[3]);
                mma_fp8(rc_acc[2], haf, hcf[0], hcf[1]);
                mma_fp8(rc_acc[3], haf, hcf[2], hcf[3]);
            }
            cp_wait2();
            __syncthreads();
#pragma unroll
            for (int kk = 4; kk < 8; kk++) {
                unsigned haf[4];
                unsigned hbf[4];
                unsigned hcf[4];
                ldsm4(rc_ha + kk * 32, haf);
                ldsm4(rc_wh0 + kk * 32, hbf);
                ldsm4(rc_wh1 + kk * 32, hcf);
                mma_fp8(rc_acc[0], haf, hbf[0], hbf[1]);
                mma_fp8(rc_acc[1], haf, hbf[2], hbf[3]);
                mma_fp8(rc_acc[2], haf, hcf[0], hcf[1]);
                mma_fp8(rc_acc[3], haf, hcf[2], hcf[3]);
            }
            cp_wait1();
            __syncthreads();
#pragma unroll
            for (int kk = 8; kk < 12; kk++) {
                unsigned haf[4];
                unsigned hbf[4];
                unsigned hcf[4];
                ldsm4(rc_ha + kk * 32, haf);
                ldsm4(rc_wh0 + kk * 32, hbf);
                ldsm4(rc_wh1 + kk * 32, hcf);
                mma_fp8(rc_acc[0], haf, hbf[0], hbf[1]);
                mma_fp8(rc_acc[1], haf, hbf[2], hbf[3]);
                mma_fp8(rc_acc[2], haf, hcf[0], hcf[1]);
                mma_fp8(rc_acc[3], haf, hcf[2], hcf[3]);
            }
            cp_wait0();
            __syncthreads();
#pragma unroll
            for (int kk = 12; kk < 16; kk++) {
                unsigned haf[4];
                unsigned hbf[4];
                unsigned hcf[4];
                ldsm4(rc_ha + kk * 32, haf);
                ldsm4(rc_wh0 + kk * 32, hbf);
                ldsm4(rc_wh1 + kk * 32, hcf);
                mma_fp8(rc_acc[0], haf, hbf[0], hbf[1]);
                mma_fp8(rc_acc[1], haf, hbf[2], hbf[3]);
                mma_fp8(rc_acc[2], haf, hcf[0], hcf[1]);
                mma_fp8(rc_acc[3], haf, hcf[2], hcf[3]);
            }
        } else {
#pragma unroll
            for (int ks = 0; ks < 8; ks++) {
                unsigned xaf[4];
                unsigned xbf[4];
                unsigned xcf[4];
                ldsm4(xcur + ks * 32, xaf);
                ldsm4(rc_wx0 + ks * 32, xbf);
                ldsm4(rc_wx1 + ks * 32, xcf);
                mma_fp8(rc_acc[0], xaf, xbf[0], xbf[1]);
                mma_fp8(rc_acc[1], xaf, xbf[2], xbf[3]);
                mma_fp8(rc_acc[2], xaf, xcf[0], xcf[1]);
                mma_fp8(rc_acc[3], xaf, xcf[2], xcf[3]);
            }
            cp_wait0();
            __syncthreads();
        }

        // epilogue: gates = acc/1024 + bias  (X*16 * W*64, h*16 * W*64)
        float rc_h[4];
#pragma unroll
        for (int pp = 0; pp < 4; pp++) {
            const float ksc = 0.0009765625f;
            float pgi = rc_acc[0][pp] * ksc + bias_r[0][pp & 1];
            float pgf = rc_acc[1][pp] * ksc + bias_r[1][pp & 1];
            float pgg = rc_acc[2][pp] * ksc + bias_r[2][pp & 1];
            float pgo = rc_acc[3][pp] * ksc + bias_r[3][pp & 1];
            float piv = sigmoid_fast(pgi);
            float pfv = sigmoid_fast(pgf);
            float pgv = tanh_fast(pgg);
            float pov = sigmoid_fast(pgo);
            rc_c[pp] = pfv * rc_c[pp] + piv * pgv;
            rc_h[pp] = pov * tanh_fast(rc_c[pp]);
        }

        const size_t rc_ho = ((size_t)(dir * TT + t) * BB + rc_bl) * HH + hc0 + 2 * rc_q;
        __nv_fp8x2_e4m3 rc_p01(make_float2(rc_h[0] * 16.0f, rc_h[1] * 16.0f));
        __nv_fp8x2_e4m3 rc_p23(make_float2(rc_h[2] * 16.0f, rc_h[3] * 16.0f));
        *(unsigned short*)(g_h8 + rc_ho) = *(unsigned short*)&rc_p01;
        *(unsigned short*)(g_h8 + rc_ho + 8 * HH) = *(unsigned short*)&rc_p23;

        __syncthreads();
        if (rc_tid == 0) {
            asm volatile("red.release.gpu.global.add.u32 [%0], %1;"
                         :: "l"(&g_flag[dir * 4 + rc_myck]), "r"(1u) : "memory");
        }
    }
}

// =============== kernel 3: emissions, warp per (t, 4 b's) ===========================
__global__ void __launch_bounds__(128) emissions_k(
    const float* __restrict__ linW, const float* __restrict__ linb)
{
    const int em_t = blockIdx.y;
    const int em_b0 = (blockIdx.x * 4 + (threadIdx.x >> 5)) * 4;
    const int em_lane = threadIdx.x & 31;

    float em_acc[4][NK];
#pragma unroll
    for (int bb = 0; bb < 4; bb++) {
#pragma unroll
        for (int kc = 0; kc < NK; kc++) em_acc[bb][kc] = 0.0f;
    }

#pragma unroll
    for (int dd = 0; dd < 2; dd++) {
        unsigned hw[4][4];
#pragma unroll
        for (int bb = 0; bb < 4; bb++) {
            uint4 hv = *(const uint4*)(g_h8 +
                ((size_t)(dd * TT + em_t) * BB + em_b0 + bb) * HH + em_lane * 16);
            hw[bb][0] = hv.x;
            hw[bb][1] = hv.y;
            hw[bb][2] = hv.z;
            hw[bb][3] = hv.w;
        }
        const float* wb = linW + dd * HH + em_lane * 16;
#pragma unroll
        for (int sub = 0; sub < 4; sub++) {
            float hfb[4][4];
#pragma unroll
            for (int bb = 0; bb < 4; bb++) {
                unsigned wd = hw[bb][sub];
                float2 f01 = fp8x2_to_float2((unsigned short)(wd & 0xffffu));
                float2 f23 = fp8x2_to_float2((unsigned short)(wd >> 16));
                hfb[bb][0] = f01.x;
                hfb[bb][1] = f01.y;
                hfb[bb][2] = f23.x;
                hfb[bb][3] = f23.y;
            }
#pragma unroll
            for (int kc = 0; kc < NK; kc++) {
                float4 w = __ldg((const float4*)(wb + kc * (2 * HH) + sub * 4));
#pragma unroll
                for (int bb = 0; bb < 4; bb++) {
                    em_acc[bb][kc] += hfb[bb][0] * w.x + hfb[bb][1] * w.y
                                    + hfb[bb][2] * w.z + hfb[bb][3] * w.w;
                }
            }
        }
    }
#pragma unroll
    for (int bb = 0; bb < 4; bb++) {
#pragma unroll
        for (int kc = 0; kc < NK; kc++) {
#pragma unroll
            for (int o = 16; o; o >>= 1)
                em_acc[bb][kc] += __shfl_xor_sync(0xffffffffu, em_acc[bb][kc], o);
        }
    }
    if (em_lane == 0) {
#pragma unroll
        for (int bb = 0; bb < 4; bb++) {
#pragma unroll
            for (int kc = 0; kc < NK; kc++) {
                g_em[((size_t)em_t * BB + em_b0 + bb) * NK + kc] =
                    em_acc[bb][kc] * 0.0625f + linb[kc];
            }
        }
    }
}

// =============== kernel 4: CRF score + forward algorithm =============================
__global__ void __launch_bounds__(32) crf_k(
    const int* __restrict__ labels, const float* __restrict__ trans,
    const float* __restrict__ startT, const float* __restrict__ endT)
{
    const int cb = blockIdx.x;
    const int cl = threadIdx.x;

    float csc = 0.0f;
    for (int ct = cl; ct < TT; ct += 32) {
        int clt = labels[cb * TT + ct];
        csc += g_em[((size_t)ct * BB + cb) * NK + clt];
        if (ct < TT - 1) csc += trans[clt * NK + labels[cb * TT + ct + 1]];
    }
#pragma unroll
    for (int o = 16; o; o >>= 1) csc += __shfl_down_sync(0xffffffffu, csc, o);

    const int ck = (cl < NK) ? cl : 0;
    float ctr[NK];
#pragma unroll
    for (int cj = 0; cj < NK; cj++) ctr[cj] = trans[cj * NK + ck];

    float calpha = startT[ck] + g_em[(size_t)cb * NK + ck];
    for (int ct = 1; ct < TT; ct++) {
        float cv[NK];
        float cm = -3.0e38f;
#pragma unroll
        for (int cj = 0; cj < NK; cj++) {
            cv[cj] = __shfl_sync(0xffffffffu, calpha, cj) + ctr[cj];
            cm = fmaxf(cm, cv[cj]);
        }
        float cs = 0.0f;
#pragma unroll
        for (int cj = 0; cj < NK; cj++) cs += __expf(cv[cj] - cm);
        calpha = cm + __logf(cs) + g_em[((size_t)ct * BB + cb) * NK + ck];
    }
    float cav = calpha + endT[ck];
    float cmm = cav;
#pragma unroll
    for (int cj = 0; cj < NK; cj++) cmm = fmaxf(cmm, __shfl_sync(0xffffffffu, cav, cj));
    float ce = (cl < NK) ? __expf(cav - cmm) : 0.0f;
#pragma unroll
    for (int o = 16; o; o >>= 1) ce += __shfl_down_sync(0xffffffffu, ce, o);

    if (cl == 0) {
        float clogZ = cmm + __logf(ce);
        float cscore = csc + startT[labels[cb * TT]] + endT[labels[cb * TT + TT - 1]];
        g_lossB[cb] = cscore - clogZ;
    }
}

// =============== kernel 5: deterministic final reduce ================================
__global__ void __launch_bounds__(128) final_reduce(float* out)
{
    __shared__ float fr_s[128];
    fr_s[threadIdx.x] = g_lossB[threadIdx.x];
    __syncthreads();
    for (int o = 64; o; o >>= 1) {
        if (threadIdx.x < o) fr_s[threadIdx.x] += fr_s[threadIdx.x + o];
        __syncthreads();
    }
    if (threadIdx.x == 0) out[0] = -fr_s[0];
}

// =============== launch ==============================================================
extern "C" void kernel_launch(void* const* d_in, const int* in_sizes, int n_in,
                              void* d_out, int out_size)
{
    const int*   inputData = (const int*)d_in[0];
    const int*   labels    = (const int*)d_in[1];
    const float* embed     = (const float*)d_in[2];
    const float* WihF = (const float*)d_in[3];
    const float* WhhF = (const float*)d_in[4];
    const float* bihF = (const float*)d_in[5];
    const float* bhhF = (const float*)d_in[6];
    const float* WihB = (const float*)d_in[7];
    const float* WhhB = (const float*)d_in[8];
    const float* bihB = (const float*)d_in[9];
    const float* bhhB = (const float*)d_in[10];
    const float* linW = (const float*)d_in[11];
    const float* linb = (const float*)d_in[12];
    const float* trans = (const float*)d_in[13];
    const float* startT = (const float*)d_in[14];
    const float* endT   = (const float*)d_in[15];

    cudaFuncSetAttribute(recurrent, cudaFuncAttributeMaxDynamicSharedMemorySize, RC_SMEM);

    reset_flags_k<<<1, 32>>>();
    embed_gather<<<dim3(TT, 16), 256>>>(inputData, embed);

    recurrent<<<NCTAS, 256, RC_SMEM>>>(WhhF, WhhB, WihF, WihB, bihF, bhhF, bihB, bhhB);

    emissions_k<<<dim3(8, TT), 128>>>(linW, linb);
    crf_k<<<BB, 32>>>(labels, trans, startT, endT);
    final_reduce<<<1, 128>>>((float*)d_out);
}